// round 1
// baseline (speedup 1.0000x reference)
#include <cuda_runtime.h>
#include <math.h>
#include <stdint.h>

#define FT 256
#define NC 16
#define NMAX 100000
#define G2 592            // 4 blocks/SM * 148 SMs
#define TILE_ROWS 32

typedef unsigned long long ull;

// -------- device scratch (static; no allocation allowed) --------
__device__ float  g_coef[FT];
__device__ float  g_rawretT[(size_t)FT * NMAX];     // column-major [col][row]  (102.4 MB)
__device__ float  g_rnorm[NMAX];
__device__ float  g_partial[(size_t)G2 * NC * FT];  // per-block class partial sums (9.7 MB)
__device__ float2 g_ave2[FT * NC];                  // duplicated ave, layout [col][cls]
__device__ float  g_avenorm[NC];

__device__ __forceinline__ float eluf(float x) {
    return x > 0.f ? x : (__expf(x) - 1.f);
}

// ---------------- kernel 1: tiny setup (coef vector) ----------------
__global__ void k_setup(const float* __restrict__ p1, const float* __restrict__ p2,
                        const float* __restrict__ p3, const float* __restrict__ wwp,
                        const float* __restrict__ wwf, const float* __restrict__ wdp) {
    int j = threadIdx.x;
    float s = wwp[0] * p1[j] + wwp[1] * p2[j] + wwp[2] * p3[j];
    float w = 1.f + (s > 0.f ? s : (expf(s) - 1.f));
    g_coef[j] = wwf[0] * w + wwf[1] * wdp[j];
}

// ---------------- kernel 2: pointwise + transpose + class partials ----------------
// Per 32-row tile:
//   A : warp-per-row (4 rows/warp), coalesced LDG.128 of seq/seq1, elu, row sumsq,
//       store to XOR-swizzled smem tile (float4 slot = c4 ^ row)
//   B1: transposed write to column-major scratch (lane <-> row, coalesced STG.32)
//   B2: class sums, thread <-> column (exclusive smem accumulator, zero conflicts)
__global__ void __launch_bounds__(256, 4)
k_main(const float4* __restrict__ seq4, const float4* __restrict__ seq14,
       const int* __restrict__ labels, const float* __restrict__ a4p,
       int N, int ntiles) {
    extern __shared__ float sm[];
    float4* s_tile = (float4*)sm;                  // 32 x 64 float4 = 32 KB
    float*  s_acc  = sm + 8192;                    // 16 x 256 = 16 KB
    int*    s_lab  = (int*)(sm + 8192 + 4096);     // 32 ints

    int tid  = threadIdx.x;
    int lane = tid & 31;
    int warp = tid >> 5;
    float a4 = a4p[0];

    for (int i = tid; i < NC * FT; i += 256) s_acc[i] = 0.f;
    float4 cA = ((const float4*)g_coef)[lane];        // coef cols 4*lane..+3
    float4 cB = ((const float4*)g_coef)[lane + 32];   // coef cols 128+4*lane..+3
    __syncthreads();

    for (int tile = blockIdx.x; tile < ntiles; tile += gridDim.x) {
        int base = tile * TILE_ROWS;
        if (tid < 32) s_lab[tid] = labels[base + tid];

        // ---- phase A ----
        #pragma unroll
        for (int q = 0; q < 4; q++) {
            int rloc = warp * 4 + q;
            size_t row = (size_t)base + rloc;
            float4 xa = seq4 [row * 64 + lane];
            float4 xb = seq4 [row * 64 + 32 + lane];
            float4 ya = seq14[row * 64 + lane];
            float4 yb = seq14[row * 64 + 32 + lane];
            float4 ra, rb;
            ra.x = fmaf(a4, ya.x, eluf(cA.x * xa.x));
            ra.y = fmaf(a4, ya.y, eluf(cA.y * xa.y));
            ra.z = fmaf(a4, ya.z, eluf(cA.z * xa.z));
            ra.w = fmaf(a4, ya.w, eluf(cA.w * xa.w));
            rb.x = fmaf(a4, yb.x, eluf(cB.x * xb.x));
            rb.y = fmaf(a4, yb.y, eluf(cB.y * xb.y));
            rb.z = fmaf(a4, yb.z, eluf(cB.z * xb.z));
            rb.w = fmaf(a4, yb.w, eluf(cB.w * xb.w));
            float ss = ra.x*ra.x + ra.y*ra.y + ra.z*ra.z + ra.w*ra.w
                     + rb.x*rb.x + rb.y*rb.y + rb.z*rb.z + rb.w*rb.w;
            #pragma unroll
            for (int o = 16; o; o >>= 1) ss += __shfl_xor_sync(0xffffffffu, ss, o);
            if (lane == 0) g_rnorm[row] = sqrtf(ss);
            s_tile[rloc * 64 + (lane        ^ rloc)] = ra;   // swizzled store
            s_tile[rloc * 64 + ((lane + 32) ^ rloc)] = rb;
        }
        __syncthreads();

        // ---- phase B1: transpose write (coalesced STG.32, lanes = rows) ----
        {
            int r = tid & 31, c4b = tid >> 5;
            #pragma unroll
            for (int k = 0; k < 8; k++) {
                int c4 = c4b * 8 + k;
                float4 v = s_tile[r * 64 + (c4 ^ r)];
                size_t o = (size_t)(c4 * 4) * N + base + r;
                g_rawretT[o]                 = v.x;
                g_rawretT[o + (size_t)N]     = v.y;
                g_rawretT[o + 2 * (size_t)N] = v.z;
                g_rawretT[o + 3 * (size_t)N] = v.w;
            }
        }

        // ---- phase B2: class partial sums (thread = column, exclusive) ----
        {
            const float* tf = sm;
            int c4s = tid >> 2;
            int k   = tid & 3;
            #pragma unroll 4
            for (int r = 0; r < TILE_ROWS; r++) {
                int lab = s_lab[r];
                float v = tf[(r * 64 + (c4s ^ r)) * 4 + k];
                s_acc[lab * FT + tid] += v;
            }
        }
        __syncthreads();
    }

    size_t pb = (size_t)blockIdx.x * (NC * FT);
    for (int i = tid; i < NC * FT; i += 256) g_partial[pb + i] = s_acc[i];
}

// ---------------- kernel 3: reduce partials -> ave, avenorm ----------------
__global__ void k_reduce(const int* __restrict__ labels, int N) {
    __shared__ float s_red[256];
    __shared__ int   s_redi[256];
    __shared__ int   s_cnt;
    int cls = blockIdx.x, tid = threadIdx.x;

    // class count (histogram of labels)
    int c = 0;
    for (int i = tid; i < N; i += 256) c += (labels[i] == cls);
    s_redi[tid] = c;
    __syncthreads();
    #pragma unroll
    for (int o = 128; o; o >>= 1) {
        if (tid < o) s_redi[tid] += s_redi[tid + o];
        __syncthreads();
    }
    if (tid == 0) s_cnt = s_redi[0];

    // sum partials over G2 blocks (coalesced)
    float s = 0.f;
    for (int b = 0; b < G2; b++)
        s += g_partial[(size_t)b * (NC * FT) + cls * FT + tid];
    __syncthreads();

    float ave = s / fmaxf((float)s_cnt, 1.f);
    g_ave2[tid * NC + cls] = make_float2(ave, ave);  // duplicated for f32x2, [col][cls]

    s_red[tid] = ave * ave;
    __syncthreads();
    #pragma unroll
    for (int o = 128; o; o >>= 1) {
        if (tid < o) s_red[tid] += s_red[tid + o];
        __syncthreads();
    }
    if (tid == 0) g_avenorm[cls] = sqrtf(s_red[0]);
}

// ---------------- kernel 4: dots (f32x2) + cosine + softmax ----------------
// thread = 2 rows (packed in f32x2 lanes); coalesced LDG.64 from column-major scratch
__global__ void __launch_bounds__(128)
k_out(float* __restrict__ out, int N) {
    __shared__ float2 s_ave[FT * NC];   // 32 KB, [col][cls], each half duplicated
    __shared__ float  s_an[NC];
    int tid = threadIdx.x;
    for (int i = tid; i < (FT * NC) / 2; i += 128)
        ((float4*)s_ave)[i] = ((const float4*)g_ave2)[i];
    if (tid < NC) s_an[tid] = g_avenorm[tid];
    __syncthreads();

    int i0 = (blockIdx.x * 128 + tid) * 2;
    if (i0 >= N) return;

    ull acc[NC];
    #pragma unroll
    for (int k2 = 0; k2 < NC; k2++) acc[k2] = 0ull;

    const float* base = g_rawretT + i0;
    #pragma unroll 2
    for (int cc = 0; cc < FT; cc++) {
        ull v = *(const ull*)(base + (size_t)cc * N);       // rows (i0, i0+1), col cc
        const float2* av = s_ave + cc * NC;
        #pragma unroll
        for (int k2 = 0; k2 < NC; k2 += 2) {
            ulonglong2 a2 = *(const ulonglong2*)(av + k2);  // LDS.128 broadcast
            asm("fma.rn.f32x2 %0, %1, %2, %0;" : "+l"(acc[k2])   : "l"(v), "l"(a2.x));
            asm("fma.rn.f32x2 %0, %1, %2, %0;" : "+l"(acc[k2+1]) : "l"(v), "l"(a2.y));
        }
    }

    float rn0 = g_rnorm[i0], rn1 = g_rnorm[i0 + 1];
    float r0[NC], r1[NC];
    #pragma unroll
    for (int k2 = 0; k2 < NC; k2++) {
        float2 a = *(float2*)&acc[k2];
        float an = s_an[k2];
        r0[k2] = a.x / fmaxf(rn0 * an, 1e-8f);
        r1[k2] = a.y / fmaxf(rn1 * an, 1e-8f);
    }
    float m0 = r0[0], m1 = r1[0];
    #pragma unroll
    for (int k2 = 1; k2 < NC; k2++) { m0 = fmaxf(m0, r0[k2]); m1 = fmaxf(m1, r1[k2]); }
    float s0 = 0.f, s1 = 0.f;
    #pragma unroll
    for (int k2 = 0; k2 < NC; k2++) {
        r0[k2] = __expf(r0[k2] - m0); s0 += r0[k2];
        r1[k2] = __expf(r1[k2] - m1); s1 += r1[k2];
    }
    float v0 = 1.f / s0, v1 = 1.f / s1;
    float4* op = (float4*)(out + (size_t)i0 * NC);
    #pragma unroll
    for (int g = 0; g < 4; g++)
        op[g]     = make_float4(r0[4*g]*v0, r0[4*g+1]*v0, r0[4*g+2]*v0, r0[4*g+3]*v0);
    #pragma unroll
    for (int g = 0; g < 4; g++)
        op[4 + g] = make_float4(r1[4*g]*v1, r1[4*g+1]*v1, r1[4*g+2]*v1, r1[4*g+3]*v1);
}

// ---------------- launcher ----------------
extern "C" void kernel_launch(void* const* d_in, const int* in_sizes, int n_in,
                              void* d_out, int out_size) {
    const float* seq    = (const float*)d_in[0];
    const float* seq1   = (const float*)d_in[1];
    const int*   labels = (const int*)  d_in[2];
    const float* p1     = (const float*)d_in[3];
    const float* p2     = (const float*)d_in[4];
    const float* p3     = (const float*)d_in[5];
    const float* wwp    = (const float*)d_in[6];
    const float* wwf    = (const float*)d_in[7];
    const float* wdp    = (const float*)d_in[8];
    const float* a4     = (const float*)d_in[9];
    float* out = (float*)d_out;

    int N = in_sizes[0] / FT;
    if (N > NMAX) N = NMAX;
    int ntiles = N / TILE_ROWS;                    // N = 100000 = 3125 * 32 exactly

    int smem2 = (8192 + 4096) * 4 + 32 * 4;        // 49280 B > 48 KB -> opt-in
    cudaFuncSetAttribute(k_main, cudaFuncAttributeMaxDynamicSharedMemorySize, smem2);

    k_setup<<<1, FT>>>(p1, p2, p3, wwp, wwf, wdp);
    k_main<<<G2, 256, smem2>>>((const float4*)seq, (const float4*)seq1, labels, a4, N, ntiles);
    k_reduce<<<NC, 256>>>(labels, N);
    k_out<<<(N / 2 + 127) / 128, 128>>>(out, N);
}

// round 2
// speedup vs baseline: 1.2342x; 1.2342x over previous
#include <cuda_runtime.h>
#include <cuda_fp16.h>
#include <math.h>
#include <stdint.h>

#define FT 256
#define NC 16
#define NMAX 100000
#define NPMAX (NMAX / 2)
#define G2 592            // 4 blocks/SM * 148 SMs
#define TILE_ROWS 32

typedef unsigned long long ull;

// -------- device scratch (static; no allocation allowed) --------
__device__ __half2 g_rawH2[(size_t)FT * NPMAX];     // column-major [col][pair], 51.2 MB
__device__ float   g_rnorm[NMAX];
__device__ float   g_partial[(size_t)G2 * NC * FT]; // per-block class partial sums
__device__ float2  g_ave2[FT * NC];                 // duplicated ave, layout [col][cls]
__device__ float   g_avenorm[NC];

__device__ __forceinline__ float eluf(float x) {
    return x > 0.f ? x : (__expf(x) - 1.f);
}
__device__ __forceinline__ ull pack2(float x, float y) {
    ull r; asm("mov.b64 %0,{%1,%2};" : "=l"(r) : "f"(x), "f"(y)); return r;
}

// ---------------- kernel 1: pointwise + transpose(fp16) + class partials ----------------
__global__ void __launch_bounds__(256, 4)
k_main(const float4* __restrict__ seq4, const float4* __restrict__ seq14,
       const int* __restrict__ labels,
       const float4* __restrict__ p14, const float4* __restrict__ p24,
       const float4* __restrict__ p34, const float* __restrict__ wwp,
       const float* __restrict__ wwf, const float4* __restrict__ wdp4,
       const float* __restrict__ a4p, int N, int ntiles) {
    extern __shared__ float sm[];
    float4* s_tile = (float4*)sm;                  // 32 x 64 float4 = 32 KB
    float*  s_acc  = sm + 8192;                    // 16 x 256 = 16 KB
    int*    s_lab  = (int*)(sm + 8192 + 4096);     // 32 ints

    int tid  = threadIdx.x;
    int lane = tid & 31;
    int warp = tid >> 5;
    float a4 = a4p[0];
    int NP = N >> 1;

    for (int i = tid; i < NC * FT; i += 256) s_acc[i] = 0.f;

    // compute coef for this thread's 8 columns (redundant per block, L2-hit)
    float wp0 = wwp[0], wp1 = wwp[1], wp2 = wwp[2];
    float f0 = wwf[0], f1 = wwf[1];
    float4 cA, cB;
    {
        float4 q1 = p14[lane], q2 = p24[lane], q3 = p34[lane], qd = wdp4[lane];
        float s;
        s = wp0*q1.x + wp1*q2.x + wp2*q3.x; cA.x = f0*(s > 0.f ? s+1.f : __expf(s)) + f1*qd.x;
        s = wp0*q1.y + wp1*q2.y + wp2*q3.y; cA.y = f0*(s > 0.f ? s+1.f : __expf(s)) + f1*qd.y;
        s = wp0*q1.z + wp1*q2.z + wp2*q3.z; cA.z = f0*(s > 0.f ? s+1.f : __expf(s)) + f1*qd.z;
        s = wp0*q1.w + wp1*q2.w + wp2*q3.w; cA.w = f0*(s > 0.f ? s+1.f : __expf(s)) + f1*qd.w;
        q1 = p14[lane+32]; q2 = p24[lane+32]; q3 = p34[lane+32]; qd = wdp4[lane+32];
        s = wp0*q1.x + wp1*q2.x + wp2*q3.x; cB.x = f0*(s > 0.f ? s+1.f : __expf(s)) + f1*qd.x;
        s = wp0*q1.y + wp1*q2.y + wp2*q3.y; cB.y = f0*(s > 0.f ? s+1.f : __expf(s)) + f1*qd.y;
        s = wp0*q1.z + wp1*q2.z + wp2*q3.z; cB.z = f0*(s > 0.f ? s+1.f : __expf(s)) + f1*qd.z;
        s = wp0*q1.w + wp1*q2.w + wp2*q3.w; cB.w = f0*(s > 0.f ? s+1.f : __expf(s)) + f1*qd.w;
    }
    __syncthreads();

    for (int tile = blockIdx.x; tile < ntiles; tile += gridDim.x) {
        int base = tile * TILE_ROWS;
        if (tid < 32) s_lab[tid] = labels[base + tid];

        // ---- phase A: pointwise, row norms, swizzled smem tile ----
        #pragma unroll
        for (int q = 0; q < 4; q++) {
            int rloc = warp * 4 + q;
            size_t row = (size_t)base + rloc;
            float4 xa = seq4 [row * 64 + lane];
            float4 xb = seq4 [row * 64 + 32 + lane];
            float4 ya = seq14[row * 64 + lane];
            float4 yb = seq14[row * 64 + 32 + lane];
            float4 ra, rb;
            ra.x = fmaf(a4, ya.x, eluf(cA.x * xa.x));
            ra.y = fmaf(a4, ya.y, eluf(cA.y * xa.y));
            ra.z = fmaf(a4, ya.z, eluf(cA.z * xa.z));
            ra.w = fmaf(a4, ya.w, eluf(cA.w * xa.w));
            rb.x = fmaf(a4, yb.x, eluf(cB.x * xb.x));
            rb.y = fmaf(a4, yb.y, eluf(cB.y * xb.y));
            rb.z = fmaf(a4, yb.z, eluf(cB.z * xb.z));
            rb.w = fmaf(a4, yb.w, eluf(cB.w * xb.w));
            float ss = ra.x*ra.x + ra.y*ra.y + ra.z*ra.z + ra.w*ra.w
                     + rb.x*rb.x + rb.y*rb.y + rb.z*rb.z + rb.w*rb.w;
            #pragma unroll
            for (int o = 16; o; o >>= 1) ss += __shfl_xor_sync(0xffffffffu, ss, o);
            if (lane == 0) g_rnorm[row] = sqrtf(ss);
            s_tile[rloc * 64 + (lane        ^ rloc)] = ra;   // swizzled store
            s_tile[rloc * 64 + ((lane + 32) ^ rloc)] = rb;
        }
        __syncthreads();

        // ---- phase B1: transpose + fp16 pack, write half2 (rows r,r+1) ----
        {
            int pr  = tid & 15;          // local pair 0..15
            int c4b = tid >> 4;          // 0..15
            int r0 = pr * 2, r1 = r0 + 1;
            int pbase = base >> 1;
            #pragma unroll
            for (int k = 0; k < 4; k++) {
                int c4 = c4b + 16 * k;
                float4 v0 = s_tile[r0 * 64 + (c4 ^ r0)];
                float4 v1 = s_tile[r1 * 64 + (c4 ^ r1)];
                size_t o = (size_t)(c4 * 4) * NP + pbase + pr;
                g_rawH2[o]                  = __floats2half2_rn(v0.x, v1.x);
                g_rawH2[o + (size_t)NP]     = __floats2half2_rn(v0.y, v1.y);
                g_rawH2[o + 2 * (size_t)NP] = __floats2half2_rn(v0.z, v1.z);
                g_rawH2[o + 3 * (size_t)NP] = __floats2half2_rn(v0.w, v1.w);
            }
        }

        // ---- phase B2: class partial sums (thread = column, exclusive) ----
        {
            const float* tf = sm;
            int c4s = tid >> 2;
            int k   = tid & 3;
            #pragma unroll 4
            for (int r = 0; r < TILE_ROWS; r++) {
                int lab = s_lab[r];
                float v = tf[(r * 64 + (c4s ^ r)) * 4 + k];
                s_acc[lab * FT + tid] += v;
            }
        }
        __syncthreads();
    }

    size_t pb = (size_t)blockIdx.x * (NC * FT);
    for (int i = tid; i < NC * FT; i += 256) g_partial[pb + i] = s_acc[i];
}

// ---------------- kernel 2: reduce partials -> ave, avenorm ----------------
__global__ void k_reduce(const int* __restrict__ labels, int N) {
    __shared__ float s_red[256];
    __shared__ int   s_redi[256];
    __shared__ int   s_cnt;
    int cls = blockIdx.x, tid = threadIdx.x;

    int c = 0;
    for (int i = tid; i < N; i += 256) c += (labels[i] == cls);
    s_redi[tid] = c;
    __syncthreads();
    #pragma unroll
    for (int o = 128; o; o >>= 1) {
        if (tid < o) s_redi[tid] += s_redi[tid + o];
        __syncthreads();
    }
    if (tid == 0) s_cnt = s_redi[0];

    float s = 0.f;
    for (int b = 0; b < G2; b++)
        s += g_partial[(size_t)b * (NC * FT) + cls * FT + tid];
    __syncthreads();

    float ave = s / fmaxf((float)s_cnt, 1.f);
    g_ave2[tid * NC + cls] = make_float2(ave, ave);

    s_red[tid] = ave * ave;
    __syncthreads();
    #pragma unroll
    for (int o = 128; o; o >>= 1) {
        if (tid < o) s_red[tid] += s_red[tid + o];
        __syncthreads();
    }
    if (tid == 0) g_avenorm[cls] = sqrtf(s_red[0]);
}

// ---------------- kernel 3: dots (f32x2) + cosine + softmax ----------------
// 256 threads = 4 column-segments x 64 row-pairs; smem reduce across segments.
__global__ void __launch_bounds__(256)
k_out(float* __restrict__ out, int N) {
    __shared__ float2 s_ave[FT * NC];        // 32 KB [col][cls], duplicated halves
    __shared__ ull    s_red[3 * 64 * NC];    // 24 KB
    __shared__ float  s_an[NC];
    int tid = threadIdx.x;
    int NP = N >> 1;

    for (int i = tid; i < (FT * NC) / 2; i += 256)
        ((float4*)s_ave)[i] = ((const float4*)g_ave2)[i];
    if (tid < NC) s_an[tid] = g_avenorm[tid];
    __syncthreads();

    int seg = tid >> 6;            // 0..3
    int p   = tid & 63;            // local pair
    int gp  = blockIdx.x * 64 + p;
    int gpc = gp < NP ? gp : NP - 1;   // clamp for loads; guard stores later

    ull acc[NC];
    #pragma unroll
    for (int k2 = 0; k2 < NC; k2++) acc[k2] = 0ull;

    const __half2* base = g_rawH2 + (size_t)(seg * 64) * NP + gpc;
    #pragma unroll 4
    for (int cc = 0; cc < 64; cc++) {
        __half2 h = base[(size_t)cc * NP];
        float2 f = __half22float2(h);
        ull v = pack2(f.x, f.y);
        const float2* av = s_ave + (seg * 64 + cc) * NC;
        #pragma unroll
        for (int k2 = 0; k2 < NC; k2 += 2) {
            ulonglong2 a2 = *(const ulonglong2*)(av + k2);
            asm("fma.rn.f32x2 %0, %1, %2, %0;" : "+l"(acc[k2])   : "l"(v), "l"(a2.x));
            asm("fma.rn.f32x2 %0, %1, %2, %0;" : "+l"(acc[k2+1]) : "l"(v), "l"(a2.y));
        }
    }

    // segment reduction: segs 1..3 dump to smem, seg 0 accumulates
    if (seg != 0) {
        ull* dst = s_red + ((seg - 1) * 64 + p) * NC;
        #pragma unroll
        for (int k2 = 0; k2 < NC; k2 += 2)
            *(ulonglong2*)(dst + k2) = make_ulonglong2(acc[k2], acc[k2+1]);
    }
    __syncthreads();
    if (seg != 0 || gp >= NP) return;

    #pragma unroll
    for (int s = 0; s < 3; s++) {
        const ull* src = s_red + (s * 64 + p) * NC;
        #pragma unroll
        for (int k2 = 0; k2 < NC; k2 += 2) {
            ulonglong2 a2 = *(const ulonglong2*)(src + k2);
            asm("add.rn.f32x2 %0, %0, %1;" : "+l"(acc[k2])   : "l"(a2.x));
            asm("add.rn.f32x2 %0, %0, %1;" : "+l"(acc[k2+1]) : "l"(a2.y));
        }
    }

    int i0 = gp * 2;
    float rn0 = g_rnorm[i0], rn1 = g_rnorm[i0 + 1];
    float r0[NC], r1[NC];
    #pragma unroll
    for (int k2 = 0; k2 < NC; k2++) {
        float2 a = *(float2*)&acc[k2];
        float an = s_an[k2];
        r0[k2] = __fdividef(a.x, fmaxf(rn0 * an, 1e-8f));
        r1[k2] = __fdividef(a.y, fmaxf(rn1 * an, 1e-8f));
    }
    float m0 = r0[0], m1 = r1[0];
    #pragma unroll
    for (int k2 = 1; k2 < NC; k2++) { m0 = fmaxf(m0, r0[k2]); m1 = fmaxf(m1, r1[k2]); }
    float s0 = 0.f, s1 = 0.f;
    #pragma unroll
    for (int k2 = 0; k2 < NC; k2++) {
        r0[k2] = __expf(r0[k2] - m0); s0 += r0[k2];
        r1[k2] = __expf(r1[k2] - m1); s1 += r1[k2];
    }
    float v0 = 1.f / s0, v1 = 1.f / s1;
    float4* op = (float4*)(out + (size_t)i0 * NC);
    #pragma unroll
    for (int g = 0; g < 4; g++)
        op[g]     = make_float4(r0[4*g]*v0, r0[4*g+1]*v0, r0[4*g+2]*v0, r0[4*g+3]*v0);
    #pragma unroll
    for (int g = 0; g < 4; g++)
        op[4 + g] = make_float4(r1[4*g]*v1, r1[4*g+1]*v1, r1[4*g+2]*v1, r1[4*g+3]*v1);
}

// ---------------- launcher ----------------
extern "C" void kernel_launch(void* const* d_in, const int* in_sizes, int n_in,
                              void* d_out, int out_size) {
    const float* seq    = (const float*)d_in[0];
    const float* seq1   = (const float*)d_in[1];
    const int*   labels = (const int*)  d_in[2];
    const float* p1     = (const float*)d_in[3];
    const float* p2     = (const float*)d_in[4];
    const float* p3     = (const float*)d_in[5];
    const float* wwp    = (const float*)d_in[6];
    const float* wwf    = (const float*)d_in[7];
    const float* wdp    = (const float*)d_in[8];
    const float* a4     = (const float*)d_in[9];
    float* out = (float*)d_out;

    int N = in_sizes[0] / FT;
    if (N > NMAX) N = NMAX;
    int ntiles = N / TILE_ROWS;
    int NP = N / 2;

    int smem2 = (8192 + 4096) * 4 + 32 * 4;
    cudaFuncSetAttribute(k_main, cudaFuncAttributeMaxDynamicSharedMemorySize, smem2);

    k_main<<<G2, 256, smem2>>>((const float4*)seq, (const float4*)seq1, labels,
                               (const float4*)p1, (const float4*)p2, (const float4*)p3,
                               wwp, wwf, (const float4*)wdp, a4, N, ntiles);
    k_reduce<<<NC, 256>>>(labels, N);
    k_out<<<(NP + 63) / 64, 256>>>(out, N);
}

// round 7
// speedup vs baseline: 1.6779x; 1.3595x over previous
#include <cuda_runtime.h>
#include <cuda_fp16.h>
#include <math.h>
#include <stdint.h>

#define FT 256
#define NC 16
#define NMAX 100000
#define G2 592            // 4 blocks/SM * 148 SMs
#define TILE_ROWS 32
#define MTILE 128

typedef unsigned long long ull;

// -------- device scratch (static; no allocation allowed) --------
__device__ __half g_rawH[(size_t)(NMAX + MTILE) * FT];  // row-major fp16 (+pad tile, zero-init)
__device__ float  g_rnorm[NMAX];
__device__ float  g_partial[(size_t)G2 * NC * FT];      // per-block class partials
__device__ __half g_aveH[NC * FT];                      // pre-swizzled B image (8KB)
__device__ float  g_avenorm[NC];

__device__ __forceinline__ float eluf(float x) {
    return x > 0.f ? x : (__expf(x) - 1.f);
}
__device__ __forceinline__ ull pack2(float x, float y) {
    ull r; asm("mov.b64 %0,{%1,%2};" : "=l"(r) : "f"(x), "f"(y)); return r;
}
__device__ __forceinline__ uint32_t smem_u32(const void* p) {
    uint32_t a;
    asm("{ .reg .u64 t; cvta.to.shared.u64 t, %1; cvt.u32.u64 %0, t; }" : "=r"(a) : "l"(p));
    return a;
}
__device__ __forceinline__ uint32_t h2u(__half2 h) {
    uint32_t u; asm("mov.b32 %0, %1;" : "=r"(u) : "r"(*(uint32_t*)&h)); return *(uint32_t*)&h;
}

// ============ kernel 1: pointwise + row-major fp16 store + class partials ============
__global__ void __launch_bounds__(256, 4)
k_main(const float4* __restrict__ seq4, const float4* __restrict__ seq14,
       const int* __restrict__ labels,
       const float4* __restrict__ p14, const float4* __restrict__ p24,
       const float4* __restrict__ p34, const float* __restrict__ wwp,
       const float* __restrict__ wwf, const float4* __restrict__ wdp4,
       const float* __restrict__ a4p, int N, int ntiles) {
    extern __shared__ char smraw[];
    __half2* s_tile = (__half2*)smraw;                 // [32][128] = 16KB
    ull*     s_acc  = (ull*)(smraw + 16384);           // [2][16][128] = 32KB
    int*     s_lab  = (int*)(smraw + 16384 + 32768);   // 32 ints

    int tid  = threadIdx.x;
    int lane = tid & 31;
    int warp = tid >> 5;
    float a4 = a4p[0];

    #pragma unroll
    for (int i = tid; i < 2 * NC * 128; i += 256) s_acc[i] = 0ull;

    float wp0 = wwp[0], wp1 = wwp[1], wp2 = wwp[2];
    float f0 = wwf[0], f1 = wwf[1];
    float4 cA, cB;
    {
        float4 q1 = p14[lane], q2 = p24[lane], q3 = p34[lane], qd = wdp4[lane];
        float s;
        s = wp0*q1.x + wp1*q2.x + wp2*q3.x; cA.x = f0*(s > 0.f ? s+1.f : __expf(s)) + f1*qd.x;
        s = wp0*q1.y + wp1*q2.y + wp2*q3.y; cA.y = f0*(s > 0.f ? s+1.f : __expf(s)) + f1*qd.y;
        s = wp0*q1.z + wp1*q2.z + wp2*q3.z; cA.z = f0*(s > 0.f ? s+1.f : __expf(s)) + f1*qd.z;
        s = wp0*q1.w + wp1*q2.w + wp2*q3.w; cA.w = f0*(s > 0.f ? s+1.f : __expf(s)) + f1*qd.w;
        q1 = p14[lane+32]; q2 = p24[lane+32]; q3 = p34[lane+32]; qd = wdp4[lane+32];
        s = wp0*q1.x + wp1*q2.x + wp2*q3.x; cB.x = f0*(s > 0.f ? s+1.f : __expf(s)) + f1*qd.x;
        s = wp0*q1.y + wp1*q2.y + wp2*q3.y; cB.y = f0*(s > 0.f ? s+1.f : __expf(s)) + f1*qd.y;
        s = wp0*q1.z + wp1*q2.z + wp2*q3.z; cB.z = f0*(s > 0.f ? s+1.f : __expf(s)) + f1*qd.z;
        s = wp0*q1.w + wp1*q2.w + wp2*q3.w; cB.w = f0*(s > 0.f ? s+1.f : __expf(s)) + f1*qd.w;
    }
    __syncthreads();

    for (int tile = blockIdx.x; tile < ntiles; tile += gridDim.x) {
        int base = tile * TILE_ROWS;
        if (tid < 32) s_lab[tid] = labels[base + tid];

        // ---- phase A: pointwise, row norms, fp16 pack -> smem + global row-major ----
        #pragma unroll
        for (int q = 0; q < 4; q++) {
            int rloc = warp * 4 + q;
            size_t row = (size_t)base + rloc;
            float4 xa = seq4 [row * 64 + lane];
            float4 xb = seq4 [row * 64 + 32 + lane];
            float4 ya = seq14[row * 64 + lane];
            float4 yb = seq14[row * 64 + 32 + lane];
            float4 ra, rb;
            ra.x = fmaf(a4, ya.x, eluf(cA.x * xa.x));
            ra.y = fmaf(a4, ya.y, eluf(cA.y * xa.y));
            ra.z = fmaf(a4, ya.z, eluf(cA.z * xa.z));
            ra.w = fmaf(a4, ya.w, eluf(cA.w * xa.w));
            rb.x = fmaf(a4, yb.x, eluf(cB.x * xb.x));
            rb.y = fmaf(a4, yb.y, eluf(cB.y * xb.y));
            rb.z = fmaf(a4, yb.z, eluf(cB.z * xb.z));
            rb.w = fmaf(a4, yb.w, eluf(cB.w * xb.w));
            float ss = ra.x*ra.x + ra.y*ra.y + ra.z*ra.z + ra.w*ra.w
                     + rb.x*rb.x + rb.y*rb.y + rb.z*rb.z + rb.w*rb.w;
            #pragma unroll
            for (int o = 16; o; o >>= 1) ss += __shfl_xor_sync(0xffffffffu, ss, o);
            if (lane == 0) g_rnorm[row] = sqrtf(ss);

            __half2 h0 = __floats2half2_rn(ra.x, ra.y);
            __half2 h1 = __floats2half2_rn(ra.z, ra.w);
            __half2 h2 = __floats2half2_rn(rb.x, rb.y);
            __half2 h3 = __floats2half2_rn(rb.z, rb.w);
            // explicit 8-byte packs (the old *(uint2*)&h0 read past the 4-byte local: UB)
            uint2 w0; w0.x = *(uint32_t*)&h0; w0.y = *(uint32_t*)&h1;
            uint2 w1; w1.x = *(uint32_t*)&h2; w1.y = *(uint32_t*)&h3;
            *(uint2*)(s_tile + rloc * 128 + 2 * lane)      = w0;
            *(uint2*)(s_tile + rloc * 128 + 64 + 2 * lane) = w1;
            ((uint2*)(g_rawH + row * FT))[lane]      = w0;
            ((uint2*)(g_rawH + row * FT))[32 + lane] = w1;
        }
        __syncthreads();

        // ---- phase B: class partial sums (thread = (colpair, rowgroup), exclusive) ----
        {
            int c2 = tid & 127;
            int rg = tid >> 7;
            ull* accb = s_acc + (size_t)rg * NC * 128 + c2;
            #pragma unroll
            for (int rr = 0; rr < 16; rr++) {
                int r = rg * 16 + rr;
                int lab = s_lab[r];
                __half2 h = s_tile[r * 128 + c2];
                float2 f = __half22float2(h);
                ull v = pack2(f.x, f.y);
                ull* a = accb + lab * 128;
                ull old = *a;
                asm("add.rn.f32x2 %0, %0, %1;" : "+l"(old) : "l"(v));
                *a = old;
            }
        }
        __syncthreads();
    }

    {
        ull* gp = (ull*)g_partial + (size_t)blockIdx.x * (NC * 128);
        #pragma unroll
        for (int i = tid; i < NC * 128; i += 256) {
            ull a = s_acc[i], b = s_acc[NC * 128 + i];
            asm("add.rn.f32x2 %0, %0, %1;" : "+l"(a) : "l"(b));
            gp[i] = a;
        }
    }
}

// ============ kernel 2: reduce partials -> ave (fp16, swizzled B image), avenorm ============
__global__ void k_reduce(const int* __restrict__ labels, int N) {
    __shared__ float s_red[256];
    __shared__ int   s_redi[256];
    __shared__ int   s_cnt;
    int cls = blockIdx.x, tid = threadIdx.x;

    int c = 0;
    for (int i = tid; i < N; i += 256) c += (labels[i] == cls);
    s_redi[tid] = c;
    __syncthreads();
    #pragma unroll
    for (int o = 128; o; o >>= 1) {
        if (tid < o) s_redi[tid] += s_redi[tid + o];
        __syncthreads();
    }
    if (tid == 0) s_cnt = s_redi[0];

    float s = 0.f;
    #pragma unroll 8
    for (int b = 0; b < G2; b++)
        s += g_partial[(size_t)b * (NC * FT) + cls * FT + tid];
    __syncthreads();

    float ave = s / fmaxf((float)s_cnt, 1.f);
    __half hv = __float2half_rn(ave);
    float avef = __half2float(hv);

    // swizzled B image: row=cls (512B rows), 16B-chunk index XOR (cls&7)
    {
        int chunk = tid >> 3;                      // 0..31
        int off = cls * 512 + ((chunk ^ (cls & 7)) << 4) + (tid & 7) * 2;
        *(__half*)((char*)g_aveH + off) = hv;
    }

    s_red[tid] = avef * avef;
    __syncthreads();
    #pragma unroll
    for (int o = 128; o; o >>= 1) {
        if (tid < o) s_red[tid] += s_red[tid + o];
        __syncthreads();
    }
    if (tid == 0) g_avenorm[cls] = sqrtf(s_red[0]);
}

// ============ kernel 3: HMMA GEMM [128 x 16 x 256] + cosine + softmax ============
// smem: A 64KB (128 rows x 512B, chunk^row swizzle) + B 8KB (16 rows x 512B, pre-swizzled)
__global__ void __launch_bounds__(128)
k_out(float* __restrict__ out, int N) {
    extern __shared__ char sm[];
    uint32_t sA = smem_u32(sm);
    uint32_t sB = sA + 65536u;

    int tid  = threadIdx.x;
    int wid  = tid >> 5;
    int lane = tid & 31;
    int tile = blockIdx.x;

    // ---- cp.async A tile (swizzled) + B image (already swizzled) ----
    {
        const char* gA = (const char*)(g_rawH + (size_t)tile * MTILE * FT);
        #pragma unroll
        for (int it = 0; it < 32; it++) {
            int i = it * 128 + tid;                // 16B chunk id
            int row = i >> 5, chunk = i & 31;
            uint32_t off = (uint32_t)row * 512u + (uint32_t)((chunk ^ (row & 7)) << 4);
            asm volatile("cp.async.cg.shared.global [%0], [%1], 16;"
                         :: "r"(sA + off), "l"(gA + (size_t)i * 16) : "memory");
        }
        const char* gB = (const char*)g_aveH;
        #pragma unroll
        for (int it = 0; it < 4; it++) {
            int i = it * 128 + tid;
            asm volatile("cp.async.cg.shared.global [%0], [%1], 16;"
                         :: "r"(sB + i * 16), "l"(gB + (size_t)i * 16) : "memory");
        }
        asm volatile("cp.async.commit_group;" ::: "memory");
        asm volatile("cp.async.wait_group 0;" ::: "memory");
    }
    __syncthreads();

    // ---- mma.sync m16n8k16: per warp 32 rows (2 m-tiles), 2 n-tiles, 16 k-steps ----
    float c00[4] = {0,0,0,0}, c01[4] = {0,0,0,0};   // m-tile 0, n-tiles 0/1
    float c10[4] = {0,0,0,0}, c11[4] = {0,0,0,0};   // m-tile 1

    int sel   = lane >> 3;       // 0..3
    int lrow8 = lane & 7;
    int rA0 = wid * 32 + (sel & 1) * 8 + lrow8;     // A lane-row for m-tile 0
    int cAadd = sel >> 1;
    int rB  = (sel >> 1) * 8 + lrow8;               // B lane-row (class)
    int cBadd = sel & 1;

    #pragma unroll
    for (int k = 0; k < 16; k++) {
        int cbase = 2 * k;
        uint32_t b0, b1, b2, b3;
        {
            // B is K-major ([class][k]) -> NON-trans ldmatrix gives the col-major
            // B fragment (lane l: n = l>>2, k = 2*(l&3)+{0,1})
            uint32_t addr = sB + (uint32_t)rB * 512u
                          + (uint32_t)(((cbase + cBadd) ^ (rB & 7)) << 4);
            asm volatile("ldmatrix.sync.aligned.m8n8.x4.shared.b16 {%0,%1,%2,%3}, [%4];"
                         : "=r"(b0), "=r"(b1), "=r"(b2), "=r"(b3) : "r"(addr));
        }
        #pragma unroll
        for (int mt = 0; mt < 2; mt++) {
            int rA = rA0 + mt * 16;
            uint32_t a0, a1, a2, a3;
            uint32_t addr = sA + (uint32_t)rA * 512u
                          + (uint32_t)(((cbase + cAadd) ^ (rA & 7)) << 4);
            asm volatile("ldmatrix.sync.aligned.m8n8.x4.shared.b16 {%0,%1,%2,%3}, [%4];"
                         : "=r"(a0), "=r"(a1), "=r"(a2), "=r"(a3) : "r"(addr));
            float* cn0 = mt ? c10 : c00;
            float* cn1 = mt ? c11 : c01;
            asm volatile("mma.sync.aligned.m16n8k16.row.col.f32.f16.f16.f32 "
                         "{%0,%1,%2,%3}, {%4,%5,%6,%7}, {%8,%9}, {%0,%1,%2,%3};"
                         : "+f"(cn0[0]), "+f"(cn0[1]), "+f"(cn0[2]), "+f"(cn0[3])
                         : "r"(a0), "r"(a1), "r"(a2), "r"(a3), "r"(b0), "r"(b1));
            asm volatile("mma.sync.aligned.m16n8k16.row.col.f32.f16.f16.f32 "
                         "{%0,%1,%2,%3}, {%4,%5,%6,%7}, {%8,%9}, {%0,%1,%2,%3};"
                         : "+f"(cn1[0]), "+f"(cn1[1]), "+f"(cn1[2]), "+f"(cn1[3])
                         : "r"(a0), "r"(a1), "r"(a2), "r"(a3), "r"(b2), "r"(b3));
        }
    }

    // ---- epilogue: quad owns a row's 16 cols; cosine + softmax in registers ----
    int j2 = (lane & 3) * 2;                  // this thread's col pair base
    float an0 = __ldg(&g_avenorm[j2]);
    float an1 = __ldg(&g_avenorm[j2 + 1]);
    float an2 = __ldg(&g_avenorm[j2 + 8]);
    float an3 = __ldg(&g_avenorm[j2 + 9]);

    #pragma unroll
    for (int mt = 0; mt < 2; mt++) {
        float* cn0 = mt ? c10 : c00;
        float* cn1 = mt ? c11 : c01;
        #pragma unroll
        for (int h = 0; h < 2; h++) {         // row halves (r, r+8)
            int r = tile * MTILE + wid * 32 + mt * 16 + (lane >> 2) + h * 8;
            int rc = r < N ? r : N - 1;
            float rn = __ldg(&g_rnorm[rc]);
            float v0 = __fdividef(cn0[2*h],   fmaxf(rn * an0, 1e-8f));
            float v1 = __fdividef(cn0[2*h+1], fmaxf(rn * an1, 1e-8f));
            float v2 = __fdividef(cn1[2*h],   fmaxf(rn * an2, 1e-8f));
            float v3 = __fdividef(cn1[2*h+1], fmaxf(rn * an3, 1e-8f));
            float mx = fmaxf(fmaxf(v0, v1), fmaxf(v2, v3));
            mx = fmaxf(mx, __shfl_xor_sync(0xffffffffu, mx, 1));
            mx = fmaxf(mx, __shfl_xor_sync(0xffffffffu, mx, 2));
            v0 = __expf(v0 - mx); v1 = __expf(v1 - mx);
            v2 = __expf(v2 - mx); v3 = __expf(v3 - mx);
            float ssum = v0 + v1 + v2 + v3;
            ssum += __shfl_xor_sync(0xffffffffu, ssum, 1);
            ssum += __shfl_xor_sync(0xffffffffu, ssum, 2);
            float inv = 1.f / ssum;
            if (r < N) {
                float2* op = (float2*)(out + (size_t)r * NC);
                op[j2 >> 1]       = make_float2(v0 * inv, v1 * inv);
                op[(j2 >> 1) + 4] = make_float2(v2 * inv, v3 * inv);
            }
        }
    }
}

// ---------------- launcher ----------------
extern "C" void kernel_launch(void* const* d_in, const int* in_sizes, int n_in,
                              void* d_out, int out_size) {
    const float* seq    = (const float*)d_in[0];
    const float* seq1   = (const float*)d_in[1];
    const int*   labels = (const int*)  d_in[2];
    const float* p1     = (const float*)d_in[3];
    const float* p2     = (const float*)d_in[4];
    const float* p3     = (const float*)d_in[5];
    const float* wwp    = (const float*)d_in[6];
    const float* wwf    = (const float*)d_in[7];
    const float* wdp    = (const float*)d_in[8];
    const float* a4     = (const float*)d_in[9];
    float* out = (float*)d_out;

    int N = in_sizes[0] / FT;
    if (N > NMAX) N = NMAX;
    int ntiles = N / TILE_ROWS;                 // 100000 = 3125 * 32 exactly
    int mtiles = (N + MTILE - 1) / MTILE;       // 782

    int smem1 = 16384 + 32768 + 128;            // 49280
    int smem3 = 65536 + 8192;                   // 72KB
    cudaFuncSetAttribute(k_main, cudaFuncAttributeMaxDynamicSharedMemorySize, smem1);
    cudaFuncSetAttribute(k_out,  cudaFuncAttributeMaxDynamicSharedMemorySize, smem3);

    k_main<<<G2, 256, smem1>>>((const float4*)seq, (const float4*)seq1, labels,
                               (const float4*)p1, (const float4*)p2, (const float4*)p3,
                               wwp, wwf, (const float4*)wdp, a4, N, ntiles);
    k_reduce<<<NC, 256>>>(labels, N);
    k_out<<<mtiles, 128, smem3>>>(out, N);
}

// round 8
// speedup vs baseline: 2.1229x; 1.2652x over previous
#include <cuda_runtime.h>
#include <cuda_fp16.h>
#include <math.h>
#include <stdint.h>

#define FT 256
#define NC 16
#define NMAX 100000
#define G2 592            // 4 blocks/SM * 148 SMs
#define TILE_ROWS 32
#define MTILE 128

typedef unsigned long long ull;

// -------- device scratch (static; no allocation allowed) --------
__device__ __half g_rawH[(size_t)(NMAX + MTILE) * FT];  // row-major fp16 (+pad rows stay zero)
__device__ float  g_rnorm[NMAX];
__device__ float  g_partial[(size_t)G2 * NC * FT];      // per-block class partials
__device__ int    g_pcnt[G2 * NC];                      // per-block class counts
__device__ __half g_aveH[NC * FT];                      // pre-swizzled B image (8KB)
__device__ float  g_avenorm[NC];

__device__ __forceinline__ float eluf(float x) {
    return x > 0.f ? x : (__expf(x) - 1.f);
}
__device__ __forceinline__ ull pack2(float x, float y) {
    ull r; asm("mov.b64 %0,{%1,%2};" : "=l"(r) : "f"(x), "f"(y)); return r;
}
__device__ __forceinline__ uint32_t smem_u32(const void* p) {
    uint32_t a;
    asm("{ .reg .u64 t; cvta.to.shared.u64 t, %1; cvt.u32.u64 %0, t; }" : "=r"(a) : "l"(p));
    return a;
}

// ============ kernel 1: pointwise + fp16 store + class partials + histogram ============
__global__ void __launch_bounds__(256, 4)
k_main(const float4* __restrict__ seq4, const float4* __restrict__ seq14,
       const int* __restrict__ labels,
       const float4* __restrict__ p14, const float4* __restrict__ p24,
       const float4* __restrict__ p34, const float* __restrict__ wwp,
       const float* __restrict__ wwf, const float4* __restrict__ wdp4,
       const float* __restrict__ a4p, int N, int ntiles) {
    extern __shared__ char smraw[];
    __half2* s_tile = (__half2*)smraw;                 // [32][128] = 16KB
    ull*     s_acc  = (ull*)(smraw + 16384);           // [2][16][128] = 32KB
    int*     s_lab  = (int*)(smraw + 16384 + 32768);   // 32 ints
    int*     s_cnt  = (int*)(smraw + 16384 + 32768 + 128);  // 16 ints

    int tid  = threadIdx.x;
    int lane = tid & 31;
    int warp = tid >> 5;
    float a4 = a4p[0];

    #pragma unroll
    for (int i = tid; i < 2 * NC * 128; i += 256) s_acc[i] = 0ull;
    if (tid < NC) s_cnt[tid] = 0;

    float wp0 = wwp[0], wp1 = wwp[1], wp2 = wwp[2];
    float f0 = wwf[0], f1 = wwf[1];
    float4 cA, cB;
    {
        float4 q1 = p14[lane], q2 = p24[lane], q3 = p34[lane], qd = wdp4[lane];
        float s;
        s = wp0*q1.x + wp1*q2.x + wp2*q3.x; cA.x = f0*(s > 0.f ? s+1.f : __expf(s)) + f1*qd.x;
        s = wp0*q1.y + wp1*q2.y + wp2*q3.y; cA.y = f0*(s > 0.f ? s+1.f : __expf(s)) + f1*qd.y;
        s = wp0*q1.z + wp1*q2.z + wp2*q3.z; cA.z = f0*(s > 0.f ? s+1.f : __expf(s)) + f1*qd.z;
        s = wp0*q1.w + wp1*q2.w + wp2*q3.w; cA.w = f0*(s > 0.f ? s+1.f : __expf(s)) + f1*qd.w;
        q1 = p14[lane+32]; q2 = p24[lane+32]; q3 = p34[lane+32]; qd = wdp4[lane+32];
        s = wp0*q1.x + wp1*q2.x + wp2*q3.x; cB.x = f0*(s > 0.f ? s+1.f : __expf(s)) + f1*qd.x;
        s = wp0*q1.y + wp1*q2.y + wp2*q3.y; cB.y = f0*(s > 0.f ? s+1.f : __expf(s)) + f1*qd.y;
        s = wp0*q1.z + wp1*q2.z + wp2*q3.z; cB.z = f0*(s > 0.f ? s+1.f : __expf(s)) + f1*qd.z;
        s = wp0*q1.w + wp1*q2.w + wp2*q3.w; cB.w = f0*(s > 0.f ? s+1.f : __expf(s)) + f1*qd.w;
    }
    __syncthreads();

    for (int tile = blockIdx.x; tile < ntiles; tile += gridDim.x) {
        int base = tile * TILE_ROWS;
        if (tid < 32) {
            int lb = labels[base + tid];
            s_lab[tid] = lb;
            atomicAdd(&s_cnt[lb], 1);
        }

        // ---- phase A: pointwise, row norms, fp16 pack -> smem + global row-major ----
        #pragma unroll
        for (int q = 0; q < 4; q++) {
            int rloc = warp * 4 + q;
            size_t row = (size_t)base + rloc;
            float4 xa = seq4 [row * 64 + lane];
            float4 xb = seq4 [row * 64 + 32 + lane];
            float4 ya = seq14[row * 64 + lane];
            float4 yb = seq14[row * 64 + 32 + lane];
            float4 ra, rb;
            ra.x = fmaf(a4, ya.x, eluf(cA.x * xa.x));
            ra.y = fmaf(a4, ya.y, eluf(cA.y * xa.y));
            ra.z = fmaf(a4, ya.z, eluf(cA.z * xa.z));
            ra.w = fmaf(a4, ya.w, eluf(cA.w * xa.w));
            rb.x = fmaf(a4, yb.x, eluf(cB.x * xb.x));
            rb.y = fmaf(a4, yb.y, eluf(cB.y * xb.y));
            rb.z = fmaf(a4, yb.z, eluf(cB.z * xb.z));
            rb.w = fmaf(a4, yb.w, eluf(cB.w * xb.w));
            float ss = ra.x*ra.x + ra.y*ra.y + ra.z*ra.z + ra.w*ra.w
                     + rb.x*rb.x + rb.y*rb.y + rb.z*rb.z + rb.w*rb.w;
            #pragma unroll
            for (int o = 16; o; o >>= 1) ss += __shfl_xor_sync(0xffffffffu, ss, o);
            if (lane == 0) g_rnorm[row] = sqrtf(ss);

            __half2 h0 = __floats2half2_rn(ra.x, ra.y);
            __half2 h1 = __floats2half2_rn(ra.z, ra.w);
            __half2 h2 = __floats2half2_rn(rb.x, rb.y);
            __half2 h3 = __floats2half2_rn(rb.z, rb.w);
            uint2 w0; w0.x = *(uint32_t*)&h0; w0.y = *(uint32_t*)&h1;
            uint2 w1; w1.x = *(uint32_t*)&h2; w1.y = *(uint32_t*)&h3;
            *(uint2*)(s_tile + rloc * 128 + 2 * lane)      = w0;
            *(uint2*)(s_tile + rloc * 128 + 64 + 2 * lane) = w1;
            ((uint2*)(g_rawH + row * FT))[lane]      = w0;
            ((uint2*)(g_rawH + row * FT))[32 + lane] = w1;
        }
        __syncthreads();

        // ---- phase B: class partial sums (thread = (colpair, rowgroup), exclusive) ----
        {
            int c2 = tid & 127;
            int rg = tid >> 7;
            ull* accb = s_acc + (size_t)rg * NC * 128 + c2;
            #pragma unroll
            for (int rr = 0; rr < 16; rr++) {
                int r = rg * 16 + rr;
                int lab = s_lab[r];
                __half2 h = s_tile[r * 128 + c2];
                float2 f = __half22float2(h);
                ull v = pack2(f.x, f.y);
                ull* a = accb + lab * 128;
                ull old = *a;
                asm("add.rn.f32x2 %0, %0, %1;" : "+l"(old) : "l"(v));
                *a = old;
            }
        }
        __syncthreads();
    }

    {
        ull* gp = (ull*)g_partial + (size_t)blockIdx.x * (NC * 128);
        #pragma unroll
        for (int i = tid; i < NC * 128; i += 256) {
            ull a = s_acc[i], b = s_acc[NC * 128 + i];
            asm("add.rn.f32x2 %0, %0, %1;" : "+l"(a) : "l"(b));
            gp[i] = a;
        }
        if (tid < NC) g_pcnt[blockIdx.x * NC + tid] = s_cnt[tid];
    }
}

// ============ kernel 2: reduce partials -> ave (fp16 B image), avenorm ============
__global__ void __launch_bounds__(1024)
k_reduce() {
    __shared__ float s_part[3 * 256];
    __shared__ float s_ave2[256];
    __shared__ float s_red[8];
    __shared__ int   s_ci[32];
    __shared__ int   s_cnt;
    int cls = blockIdx.x, tid = threadIdx.x;
    int col = tid & 255, grp = tid >> 8;

    // 4-way split partial sum (148 blocks each; 592 = 4*148)
    float s = 0.f;
    const float* gp = g_partial + (size_t)cls * 256 + col + (size_t)(grp * 148) * 4096;
    #pragma unroll 4
    for (int b = 0; b < 148; b++) s += gp[(size_t)b * 4096];
    if (grp) s_part[(grp - 1) * 256 + col] = s;

    // class count from per-block integer histograms
    int c = (tid < G2) ? g_pcnt[tid * NC + cls] : 0;
    #pragma unroll
    for (int o = 16; o; o >>= 1) c += __shfl_xor_sync(0xffffffffu, c, o);
    if ((tid & 31) == 0) s_ci[tid >> 5] = c;
    __syncthreads();
    if (tid == 0) {
        int t = 0;
        #pragma unroll
        for (int i = 0; i < 32; i++) t += s_ci[i];
        s_cnt = t;
    }
    __syncthreads();

    if (grp == 0) {
        float a = (s + s_part[col] + s_part[256 + col] + s_part[512 + col])
                / fmaxf((float)s_cnt, 1.f);
        __half hv = __float2half_rn(a);
        float af = __half2float(hv);
        s_ave2[col] = af * af;
        // swizzled B image: row=cls (512B rows), 16B-chunk index XOR (cls&7)
        int chunk = col >> 3;
        int off = cls * 512 + ((chunk ^ (cls & 7)) << 4) + (col & 7) * 2;
        *(__half*)((char*)g_aveH + off) = hv;
    }
    __syncthreads();

    if (tid < 256) {
        float v = s_ave2[tid];
        #pragma unroll
        for (int o = 16; o; o >>= 1) v += __shfl_xor_sync(0xffffffffu, v, o);
        if ((tid & 31) == 0) s_red[tid >> 5] = v;
    }
    __syncthreads();
    if (tid == 0) {
        float t = 0.f;
        #pragma unroll
        for (int i = 0; i < 8; i++) t += s_red[i];
        g_avenorm[cls] = sqrtf(t);
    }
}

// ============ kernel 3: HMMA GEMM + cosine + softmax; warp-per-16-rows ============
// smem: A 64KB (8 warp slices x 8KB, chunk^row swizzle) + B 8KB (pre-swizzled)
__global__ void __launch_bounds__(256)
k_out(float* __restrict__ out, int N) {
    extern __shared__ char sm[];
    uint32_t sA = smem_u32(sm);
    uint32_t sB = sA + 65536u;

    int tid  = threadIdx.x;
    int wid  = tid >> 5;
    int lane = tid & 31;
    int rowbase = blockIdx.x * MTILE + wid * 16;

    // B image: 512 chunks, 2 per thread
    {
        const char* gB = (const char*)g_aveH;
        #pragma unroll
        for (int it = 0; it < 2; it++) {
            int i = it * 256 + tid;
            asm volatile("cp.async.cg.shared.global [%0], [%1], 16;"
                         :: "r"(sB + i * 16), "l"(gB + (size_t)i * 16) : "memory");
        }
    }
    // A warp slice: 16 rows x 512B
    {
        const char* gA = (const char*)(g_rawH + (size_t)rowbase * FT);
        uint32_t aslice = sA + (uint32_t)(wid * 8192);
        #pragma unroll
        for (int it = 0; it < 16; it++) {
            uint32_t off = aslice + (uint32_t)(it * 512) + (uint32_t)((lane ^ (it & 7)) << 4);
            asm volatile("cp.async.cg.shared.global [%0], [%1], 16;"
                         :: "r"(off), "l"(gA + (size_t)it * 512 + (size_t)lane * 16) : "memory");
        }
    }
    asm volatile("cp.async.commit_group;" ::: "memory");
    asm volatile("cp.async.wait_group 0;" ::: "memory");
    __syncthreads();

    // ---- mma.sync m16n8k16: one m16 tile per warp, 2 n-tiles, 16 k-steps ----
    float c0[4] = {0,0,0,0}, c1[4] = {0,0,0,0};
    int sel   = lane >> 3;
    int lrow8 = lane & 7;
    int lrA = (sel & 1) * 8 + lrow8;     // local A row 0..15
    int cAadd = sel >> 1;
    int rB  = (sel >> 1) * 8 + lrow8;    // B row (class)
    int cBadd = sel & 1;
    uint32_t aab = sA + (uint32_t)(wid * 8192) + (uint32_t)(lrA * 512);
    uint32_t bab = sB + (uint32_t)(rB * 512);

    #pragma unroll
    for (int k = 0; k < 16; k++) {
        int cbase = 2 * k;
        uint32_t b0, b1, b2, b3;
        uint32_t baddr = bab + (uint32_t)(((cbase + cBadd) ^ (rB & 7)) << 4);
        asm volatile("ldmatrix.sync.aligned.m8n8.x4.shared.b16 {%0,%1,%2,%3}, [%4];"
                     : "=r"(b0), "=r"(b1), "=r"(b2), "=r"(b3) : "r"(baddr));
        uint32_t a0, a1, a2, a3;
        uint32_t aaddr = aab + (uint32_t)(((cbase + cAadd) ^ (lrA & 7)) << 4);
        asm volatile("ldmatrix.sync.aligned.m8n8.x4.shared.b16 {%0,%1,%2,%3}, [%4];"
                     : "=r"(a0), "=r"(a1), "=r"(a2), "=r"(a3) : "r"(aaddr));
        asm volatile("mma.sync.aligned.m16n8k16.row.col.f32.f16.f16.f32 "
                     "{%0,%1,%2,%3}, {%4,%5,%6,%7}, {%8,%9}, {%0,%1,%2,%3};"
                     : "+f"(c0[0]), "+f"(c0[1]), "+f"(c0[2]), "+f"(c0[3])
                     : "r"(a0), "r"(a1), "r"(a2), "r"(a3), "r"(b0), "r"(b1));
        asm volatile("mma.sync.aligned.m16n8k16.row.col.f32.f16.f16.f32 "
                     "{%0,%1,%2,%3}, {%4,%5,%6,%7}, {%8,%9}, {%0,%1,%2,%3};"
                     : "+f"(c1[0]), "+f"(c1[1]), "+f"(c1[2]), "+f"(c1[3])
                     : "r"(a0), "r"(a1), "r"(a2), "r"(a3), "r"(b2), "r"(b3));
    }

    // ---- epilogue: quad owns a row's 16 cols; cosine + softmax in registers ----
    int j2 = (lane & 3) * 2;
    float an0 = __ldg(&g_avenorm[j2]);
    float an1 = __ldg(&g_avenorm[j2 + 1]);
    float an2 = __ldg(&g_avenorm[j2 + 8]);
    float an3 = __ldg(&g_avenorm[j2 + 9]);

    #pragma unroll
    for (int h = 0; h < 2; h++) {
        int r = rowbase + (lane >> 2) + h * 8;
        int rc = r < N ? r : N - 1;
        float rn = __ldg(&g_rnorm[rc]);
        float v0 = __fdividef(c0[2*h],   fmaxf(rn * an0, 1e-8f));
        float v1 = __fdividef(c0[2*h+1], fmaxf(rn * an1, 1e-8f));
        float v2 = __fdividef(c1[2*h],   fmaxf(rn * an2, 1e-8f));
        float v3 = __fdividef(c1[2*h+1], fmaxf(rn * an3, 1e-8f));
        float mx = fmaxf(fmaxf(v0, v1), fmaxf(v2, v3));
        mx = fmaxf(mx, __shfl_xor_sync(0xffffffffu, mx, 1));
        mx = fmaxf(mx, __shfl_xor_sync(0xffffffffu, mx, 2));
        v0 = __expf(v0 - mx); v1 = __expf(v1 - mx);
        v2 = __expf(v2 - mx); v3 = __expf(v3 - mx);
        float ssum = v0 + v1 + v2 + v3;
        ssum += __shfl_xor_sync(0xffffffffu, ssum, 1);
        ssum += __shfl_xor_sync(0xffffffffu, ssum, 2);
        float inv = 1.f / ssum;
        if (r < N) {
            float2* op = (float2*)(out + (size_t)r * NC);
            op[j2 >> 1]       = make_float2(v0 * inv, v1 * inv);
            op[(j2 >> 1) + 4] = make_float2(v2 * inv, v3 * inv);
        }
    }
}

// ---------------- launcher ----------------
extern "C" void kernel_launch(void* const* d_in, const int* in_sizes, int n_in,
                              void* d_out, int out_size) {
    const float* seq    = (const float*)d_in[0];
    const float* seq1   = (const float*)d_in[1];
    const int*   labels = (const int*)  d_in[2];
    const float* p1     = (const float*)d_in[3];
    const float* p2     = (const float*)d_in[4];
    const float* p3     = (const float*)d_in[5];
    const float* wwp    = (const float*)d_in[6];
    const float* wwf    = (const float*)d_in[7];
    const float* wdp    = (const float*)d_in[8];
    const float* a4     = (const float*)d_in[9];
    float* out = (float*)d_out;

    int N = in_sizes[0] / FT;
    if (N > NMAX) N = NMAX;
    int ntiles = N / TILE_ROWS;                 // 100000 = 3125 * 32 exactly
    int mtiles = (N + MTILE - 1) / MTILE;       // 782

    int smem1 = 16384 + 32768 + 128 + 64;       // tile + acc + labels + counters
    int smem3 = 65536 + 8192;                   // 72KB
    cudaFuncSetAttribute(k_main, cudaFuncAttributeMaxDynamicSharedMemorySize, smem1);
    cudaFuncSetAttribute(k_out,  cudaFuncAttributeMaxDynamicSharedMemorySize, smem3);

    k_main<<<G2, 256, smem1>>>((const float4*)seq, (const float4*)seq1, labels,
                               (const float4*)p1, (const float4*)p2, (const float4*)p3,
                               wwp, wwf, (const float4*)wdp, a4, N, ntiles);
    k_reduce<<<NC, 1024>>>();
    k_out<<<mtiles, 256, smem3>>>(out, N);
}